// round 1
// baseline (speedup 1.0000x reference)
#include <cuda_runtime.h>

typedef unsigned long long ull;

#define BATCH 256
#define SEQ   128
#define EMBD  512
#define H2D   512
#define G2D   1536
#define HIDD  1024
#define G3D   3072
#define CTXDIM 64
#define VOC   32000
#define TLEN  40
#define SOSID 2

// ---------------- scratch (device globals: no runtime allocation) ----------------
__device__ float g_gx[2][SEQ*BATCH][G2D];   // encoder gate-x per step (bias included)  ~402MB
__device__ float g_h[2][2][BATCH*H2D];      // [dir][pingpong][b*512+u]
__device__ float g_cgx[BATCH][G3D];         // decoder constant part of gx (ctx @ W + bih)
__device__ float g_hd[2][BATCH*HIDD];       // decoder hidden ping-pong
__device__ float g_logits[BATCH][VOC];
__device__ int   g_prev[BATCH];

// ---------------- helpers ----------------
__device__ __forceinline__ ull pk2(float lo, float hi){ ull r; asm("mov.b64 %0,{%1,%2};":"=l"(r):"f"(lo),"f"(hi)); return r; }
__device__ __forceinline__ void upk2(ull v, float& lo, float& hi){ asm("mov.b64 {%0,%1},%2;":"=f"(lo),"=f"(hi):"l"(v)); }
__device__ __forceinline__ ull ffma2(ull a, ull b, ull c){ ull d; asm("fma.rn.f32x2 %0,%1,%2,%3;":"=l"(d):"l"(a),"l"(b),"l"(c)); return d; }
__device__ __forceinline__ float sigf(float x){ return 1.0f/(1.0f + expf(-x)); }

// ---------------- init ----------------
__global__ __launch_bounds__(256) void k_init(){
  int i = blockIdx.x*blockDim.x + threadIdx.x;
  if (i < BATCH*H2D){ g_h[0][0][i] = 0.f; g_h[1][0][i] = 0.f; }
  if (i < BATCH*HIDD) g_hd[0][i] = 0.f;
  if (i < BATCH) g_prev[i] = SOSID;
}

// ================= encoder input GEMM (fused embedding gather) =================
// g_gx[dir][s*B+b][n] = sum_k emb[id(b, s_eff)][k] * wih[n][k] + bih[n]
__global__ __launch_bounds__(256) void k_encx(const int* __restrict__ ids, const float* __restrict__ emb,
      const float* __restrict__ wf, const float* __restrict__ bf,
      const float* __restrict__ wb, const float* __restrict__ bbias){
  const int dir = blockIdx.z;
  const float* W    = dir ? wb : wf;
  const float* bias = dir ? bbias : bf;
  __shared__ float As[16][68];
  __shared__ float Bs[16][68];
  const int t = threadIdx.x;
  const int m0 = blockIdx.y*64, n0 = blockIdx.x*64;
  const int lr = t>>2, lk4 = (t&3)*4;
  const int tx = t&15, ty = t>>4;
  const int r  = m0 + lr;
  const int ss = r >> 8, bv = r & 255;
  const int sstep = dir ? (SEQ-1-ss) : ss;
  const float* arow = emb + (size_t)ids[bv*SEQ + sstep]*EMBD;
  const float* brow = W + (size_t)(n0+lr)*EMBD;
  ull acc[4][2];
  #pragma unroll
  for(int i=0;i<4;i++){acc[i][0]=0ull;acc[i][1]=0ull;}
  for(int k0=0;k0<EMBD;k0+=16){
    float4 av = *(const float4*)(arow + k0 + lk4);
    As[lk4+0][lr]=av.x; As[lk4+1][lr]=av.y; As[lk4+2][lr]=av.z; As[lk4+3][lr]=av.w;
    float4 bv4 = *(const float4*)(brow + k0 + lk4);
    Bs[lk4+0][lr]=bv4.x; Bs[lk4+1][lr]=bv4.y; Bs[lk4+2][lr]=bv4.z; Bs[lk4+3][lr]=bv4.w;
    __syncthreads();
    #pragma unroll
    for(int k=0;k<16;k++){
      float4 a = *(const float4*)&As[k][ty*4];
      float4 b = *(const float4*)&Bs[k][tx*4];
      ull b01 = pk2(b.x,b.y), b23 = pk2(b.z,b.w);
      ull a0=pk2(a.x,a.x), a1=pk2(a.y,a.y), a2=pk2(a.z,a.z), a3=pk2(a.w,a.w);
      acc[0][0]=ffma2(a0,b01,acc[0][0]); acc[0][1]=ffma2(a0,b23,acc[0][1]);
      acc[1][0]=ffma2(a1,b01,acc[1][0]); acc[1][1]=ffma2(a1,b23,acc[1][1]);
      acc[2][0]=ffma2(a2,b01,acc[2][0]); acc[2][1]=ffma2(a2,b23,acc[2][1]);
      acc[3][0]=ffma2(a3,b01,acc[3][0]); acc[3][1]=ffma2(a3,b23,acc[3][1]);
    }
    __syncthreads();
  }
  const int c0 = n0 + tx*4;
  float4 b4 = *(const float4*)(bias + c0);
  #pragma unroll
  for(int i=0;i<4;i++){
    int row = m0 + ty*4 + i;
    float4 o; upk2(acc[i][0], o.x, o.y); upk2(acc[i][1], o.z, o.w);
    o.x+=b4.x; o.y+=b4.y; o.z+=b4.z; o.w+=b4.w;
    *(float4*)&g_gx[dir][row][c0] = o;
  }
}

// ================= encoder recurrence: one step, both dirs, fused GEMM+gates =================
// block: 64 rows x 16 hidden units (3 gates each). K=512.
__global__ __launch_bounds__(256) void k_encstep(int s,
      const float* __restrict__ whf, const float* __restrict__ bhf,
      const float* __restrict__ whb, const float* __restrict__ bhb){
  const int dir = blockIdx.z;
  const float* whh = dir ? whb : whf;
  const float* bhh = dir ? bhb : bhf;
  const int pin = s & 1, pout = pin ^ 1;
  const float* hin = g_h[dir][pin];
  float* hout = g_h[dir][pout];
  __shared__ float hs[16][68];
  __shared__ float ws[16][48];
  const int t = threadIdx.x;
  const int u0 = blockIdx.x*16, m0 = blockIdx.y*64;
  const int lr = t>>2, lk4 = (t&3)*4;
  const int unit = t&15, rg = t>>4;
  ull ar[2]={0ull,0ull}, az[2]={0ull,0ull}, an[2]={0ull,0ull};
  const int gr = t>>2;            // weight-row id 0..47 (for t<192)
  const int uu = gr/3, gg = gr%3;
  for(int k0=0;k0<H2D;k0+=16){
    float4 av = *(const float4*)(hin + (m0+lr)*H2D + k0 + lk4);
    hs[lk4+0][lr]=av.x; hs[lk4+1][lr]=av.y; hs[lk4+2][lr]=av.z; hs[lk4+3][lr]=av.w;
    if (t < 192){
      float4 wv = *(const float4*)(whh + (size_t)(gg*H2D + u0 + uu)*H2D + k0 + lk4);
      ws[lk4+0][gr]=wv.x; ws[lk4+1][gr]=wv.y; ws[lk4+2][gr]=wv.z; ws[lk4+3][gr]=wv.w;
    }
    __syncthreads();
    #pragma unroll
    for(int k=0;k<16;k++){
      float4 a = *(const float4*)&hs[k][rg*4];
      ull a01 = pk2(a.x,a.y), a23 = pk2(a.z,a.w);
      float wr=ws[k][unit*3+0], wz=ws[k][unit*3+1], wn=ws[k][unit*3+2];
      ull wr2=pk2(wr,wr), wz2=pk2(wz,wz), wn2=pk2(wn,wn);
      ar[0]=ffma2(a01,wr2,ar[0]); ar[1]=ffma2(a23,wr2,ar[1]);
      az[0]=ffma2(a01,wz2,az[0]); az[1]=ffma2(a23,wz2,az[1]);
      an[0]=ffma2(a01,wn2,an[0]); an[1]=ffma2(a23,wn2,an[1]);
    }
    __syncthreads();
  }
  const int u = u0 + unit;
  const float bhr = bhh[u], bhz = bhh[H2D+u], bhn = bhh[2*H2D+u];
  float rr[4], zz[4], nn[4];
  upk2(ar[0],rr[0],rr[1]); upk2(ar[1],rr[2],rr[3]);
  upk2(az[0],zz[0],zz[1]); upk2(az[1],zz[2],zz[3]);
  upk2(an[0],nn[0],nn[1]); upk2(an[1],nn[2],nn[3]);
  #pragma unroll
  for(int i=0;i<4;i++){
    const int row = m0 + rg*4 + i;
    const float* gx = g_gx[dir][s*BATCH + row];
    float ghr = rr[i]+bhr, ghz = zz[i]+bhz, ghn = nn[i]+bhn;
    float r_ = sigf(gx[u] + ghr);
    float z_ = sigf(gx[H2D+u] + ghz);
    float n_ = tanhf(gx[2*H2D+u] + r_*ghn);
    float ho = hin[row*H2D + u];
    hout[row*H2D + u] = (1.f - z_)*n_ + z_*ho;
  }
}

// ================= decoder constant gx part: cgx = [enc_ctx | ctxv] @ Wih[:,512:].T + bih =================
// replicates torch h_n.view(batch,-1) scramble: ctx row b<128 -> [hf[2b], hf[2b+1]]; b>=128 -> [hb[2(b-128)], hb[..+1]]
__global__ __launch_bounds__(256) void k_cgx(const float* __restrict__ ctxv,
      const float* __restrict__ dwih, const float* __restrict__ dbih){
  __shared__ float As[16][68];
  __shared__ float Bs[16][68];
  const int t = threadIdx.x;
  const int m0 = blockIdx.y*64, n0 = blockIdx.x*64;
  const int lr = t>>2, lk4 = (t&3)*4;
  const int tx = t&15, ty = t>>4;
  const int b  = m0 + lr;
  const float* brow = dwih + (size_t)(n0+lr)*1600 + 512;
  ull acc[4][2];
  #pragma unroll
  for(int i=0;i<4;i++){acc[i][0]=0ull;acc[i][1]=0ull;}
  for(int k0=0;k0<1088;k0+=16){
    int j = k0 + lk4;
    float4 av;
    if (j < 1024){
      const float* hsrc = (b < 128) ? g_h[0][0] : g_h[1][0];
      int b2 = (b < 128) ? b : b - 128;
      av = *(const float4*)(hsrc + (2*b2 + (j>=512 ? 1 : 0))*H2D + (j & 511));
    } else {
      av = *(const float4*)(ctxv + b*CTXDIM + (j - 1024));
    }
    As[lk4+0][lr]=av.x; As[lk4+1][lr]=av.y; As[lk4+2][lr]=av.z; As[lk4+3][lr]=av.w;
    float4 bv = *(const float4*)(brow + k0 + lk4);
    Bs[lk4+0][lr]=bv.x; Bs[lk4+1][lr]=bv.y; Bs[lk4+2][lr]=bv.z; Bs[lk4+3][lr]=bv.w;
    __syncthreads();
    #pragma unroll
    for(int k=0;k<16;k++){
      float4 a = *(const float4*)&As[k][ty*4];
      float4 b4 = *(const float4*)&Bs[k][tx*4];
      ull b01 = pk2(b4.x,b4.y), b23 = pk2(b4.z,b4.w);
      ull a0=pk2(a.x,a.x), a1=pk2(a.y,a.y), a2=pk2(a.z,a.z), a3=pk2(a.w,a.w);
      acc[0][0]=ffma2(a0,b01,acc[0][0]); acc[0][1]=ffma2(a0,b23,acc[0][1]);
      acc[1][0]=ffma2(a1,b01,acc[1][0]); acc[1][1]=ffma2(a1,b23,acc[1][1]);
      acc[2][0]=ffma2(a2,b01,acc[2][0]); acc[2][1]=ffma2(a2,b23,acc[2][1]);
      acc[3][0]=ffma2(a3,b01,acc[3][0]); acc[3][1]=ffma2(a3,b23,acc[3][1]);
    }
    __syncthreads();
  }
  const int c0 = n0 + tx*4;
  float4 b4 = *(const float4*)(dbih + c0);
  #pragma unroll
  for(int i=0;i<4;i++){
    int row = m0 + ty*4 + i;
    float4 o; upk2(acc[i][0], o.x, o.y); upk2(acc[i][1], o.z, o.w);
    o.x+=b4.x; o.y+=b4.y; o.z+=b4.z; o.w+=b4.w;
    *(float4*)&g_cgx[row][c0] = o;
  }
}

// ================= decoder step: fused (emb-gather GEMM K=512) + (h GEMM K=1024) + gates =================
__global__ __launch_bounds__(256) void k_dec(int step, const float* __restrict__ emb,
      const float* __restrict__ dwih, const float* __restrict__ dwhh, const float* __restrict__ dbhh){
  const int pin = step & 1, pout = pin ^ 1;
  const float* hin = g_hd[pin];
  float* hout = g_hd[pout];
  __shared__ float xs[16][68];
  __shared__ float ws[16][48];
  __shared__ int pid_s[64];
  const int t = threadIdx.x;
  const int u0 = blockIdx.x*16, m0 = blockIdx.y*64;
  if (t < 64) pid_s[t] = g_prev[m0 + t];
  const int lr = t>>2, lk4 = (t&3)*4;
  const int unit = t&15, rg = t>>4;
  const int gr = t>>2;
  const int uu = gr/3, gg = gr%3;
  ull xr[2]={0ull,0ull}, xz[2]={0ull,0ull}, xn[2]={0ull,0ull};
  ull hr[2]={0ull,0ull}, hz[2]={0ull,0ull}, hn[2]={0ull,0ull};
  __syncthreads();
  const float* arow = emb + (size_t)pid_s[lr]*EMBD;
  // phase 1: x-part (emb of prev token), K = 512, W = dec_wih cols [0,512)
  for(int k0=0;k0<EMBD;k0+=16){
    float4 av = *(const float4*)(arow + k0 + lk4);
    xs[lk4+0][lr]=av.x; xs[lk4+1][lr]=av.y; xs[lk4+2][lr]=av.z; xs[lk4+3][lr]=av.w;
    if (t < 192){
      float4 wv = *(const float4*)(dwih + (size_t)(gg*HIDD + u0 + uu)*1600 + k0 + lk4);
      ws[lk4+0][gr]=wv.x; ws[lk4+1][gr]=wv.y; ws[lk4+2][gr]=wv.z; ws[lk4+3][gr]=wv.w;
    }
    __syncthreads();
    #pragma unroll
    for(int k=0;k<16;k++){
      float4 a = *(const float4*)&xs[k][rg*4];
      ull a01 = pk2(a.x,a.y), a23 = pk2(a.z,a.w);
      float wr=ws[k][unit*3+0], wzv=ws[k][unit*3+1], wnv=ws[k][unit*3+2];
      ull wr2=pk2(wr,wr), wz2=pk2(wzv,wzv), wn2=pk2(wnv,wnv);
      xr[0]=ffma2(a01,wr2,xr[0]); xr[1]=ffma2(a23,wr2,xr[1]);
      xz[0]=ffma2(a01,wz2,xz[0]); xz[1]=ffma2(a23,wz2,xz[1]);
      xn[0]=ffma2(a01,wn2,xn[0]); xn[1]=ffma2(a23,wn2,xn[1]);
    }
    __syncthreads();
  }
  // phase 2: h-part, K = 1024, W = dec_whh
  for(int k0=0;k0<HIDD;k0+=16){
    float4 av = *(const float4*)(hin + (m0+lr)*HIDD + k0 + lk4);
    xs[lk4+0][lr]=av.x; xs[lk4+1][lr]=av.y; xs[lk4+2][lr]=av.z; xs[lk4+3][lr]=av.w;
    if (t < 192){
      float4 wv = *(const float4*)(dwhh + (size_t)(gg*HIDD + u0 + uu)*HIDD + k0 + lk4);
      ws[lk4+0][gr]=wv.x; ws[lk4+1][gr]=wv.y; ws[lk4+2][gr]=wv.z; ws[lk4+3][gr]=wv.w;
    }
    __syncthreads();
    #pragma unroll
    for(int k=0;k<16;k++){
      float4 a = *(const float4*)&xs[k][rg*4];
      ull a01 = pk2(a.x,a.y), a23 = pk2(a.z,a.w);
      float wr=ws[k][unit*3+0], wzv=ws[k][unit*3+1], wnv=ws[k][unit*3+2];
      ull wr2=pk2(wr,wr), wz2=pk2(wzv,wzv), wn2=pk2(wnv,wnv);
      hr[0]=ffma2(a01,wr2,hr[0]); hr[1]=ffma2(a23,wr2,hr[1]);
      hz[0]=ffma2(a01,wz2,hz[0]); hz[1]=ffma2(a23,wz2,hz[1]);
      hn[0]=ffma2(a01,wn2,hn[0]); hn[1]=ffma2(a23,wn2,hn[1]);
    }
    __syncthreads();
  }
  const int u = u0 + unit;
  const float bhr = dbhh[u], bhz = dbhh[HIDD+u], bhn = dbhh[2*HIDD+u];
  float fxr[4],fxz[4],fxn[4],fhr[4],fhz[4],fhn[4];
  upk2(xr[0],fxr[0],fxr[1]); upk2(xr[1],fxr[2],fxr[3]);
  upk2(xz[0],fxz[0],fxz[1]); upk2(xz[1],fxz[2],fxz[3]);
  upk2(xn[0],fxn[0],fxn[1]); upk2(xn[1],fxn[2],fxn[3]);
  upk2(hr[0],fhr[0],fhr[1]); upk2(hr[1],fhr[2],fhr[3]);
  upk2(hz[0],fhz[0],fhz[1]); upk2(hz[1],fhz[2],fhz[3]);
  upk2(hn[0],fhn[0],fhn[1]); upk2(hn[1],fhn[2],fhn[3]);
  #pragma unroll
  for(int i=0;i<4;i++){
    const int row = m0 + rg*4 + i;
    const float* cg = g_cgx[row];
    float gxr = fxr[i] + cg[u];
    float gxz = fxz[i] + cg[HIDD+u];
    float gxn = fxn[i] + cg[2*HIDD+u];
    float ghr = fhr[i] + bhr, ghz = fhz[i] + bhz, ghn = fhn[i] + bhn;
    float r_ = sigf(gxr + ghr);
    float z_ = sigf(gxz + ghz);
    float n_ = tanhf(gxn + r_*ghn);
    float ho = hin[row*HIDD + u];
    hout[row*HIDD + u] = (1.f - z_)*n_ + z_*ho;
  }
}

// ================= logits GEMM: h @ wout.T + bout =================
__global__ __launch_bounds__(256) void k_logits(int pp, const float* __restrict__ wout, const float* __restrict__ bout){
  const float* hsrc = g_hd[pp];
  __shared__ float As[16][68];
  __shared__ float Bs[16][68];
  const int t = threadIdx.x;
  const int m0 = blockIdx.y*64, n0 = blockIdx.x*64;
  const int lr = t>>2, lk4 = (t&3)*4;
  const int tx = t&15, ty = t>>4;
  const float* arow = hsrc + (size_t)(m0+lr)*HIDD;
  const float* brow = wout + (size_t)(n0+lr)*HIDD;
  ull acc[4][2];
  #pragma unroll
  for(int i=0;i<4;i++){acc[i][0]=0ull;acc[i][1]=0ull;}
  for(int k0=0;k0<HIDD;k0+=16){
    float4 av = *(const float4*)(arow + k0 + lk4);
    As[lk4+0][lr]=av.x; As[lk4+1][lr]=av.y; As[lk4+2][lr]=av.z; As[lk4+3][lr]=av.w;
    float4 bv = *(const float4*)(brow + k0 + lk4);
    Bs[lk4+0][lr]=bv.x; Bs[lk4+1][lr]=bv.y; Bs[lk4+2][lr]=bv.z; Bs[lk4+3][lr]=bv.w;
    __syncthreads();
    #pragma unroll
    for(int k=0;k<16;k++){
      float4 a = *(const float4*)&As[k][ty*4];
      float4 b = *(const float4*)&Bs[k][tx*4];
      ull b01 = pk2(b.x,b.y), b23 = pk2(b.z,b.w);
      ull a0=pk2(a.x,a.x), a1=pk2(a.y,a.y), a2=pk2(a.z,a.z), a3=pk2(a.w,a.w);
      acc[0][0]=ffma2(a0,b01,acc[0][0]); acc[0][1]=ffma2(a0,b23,acc[0][1]);
      acc[1][0]=ffma2(a1,b01,acc[1][0]); acc[1][1]=ffma2(a1,b23,acc[1][1]);
      acc[2][0]=ffma2(a2,b01,acc[2][0]); acc[2][1]=ffma2(a2,b23,acc[2][1]);
      acc[3][0]=ffma2(a3,b01,acc[3][0]); acc[3][1]=ffma2(a3,b23,acc[3][1]);
    }
    __syncthreads();
  }
  const int c0 = n0 + tx*4;
  float4 b4 = *(const float4*)(bout + c0);
  #pragma unroll
  for(int i=0;i<4;i++){
    int row = m0 + ty*4 + i;
    float4 o; upk2(acc[i][0], o.x, o.y); upk2(acc[i][1], o.z, o.w);
    o.x+=b4.x; o.y+=b4.y; o.z+=b4.z; o.w+=b4.w;
    *(float4*)&g_logits[row][c0] = o;
  }
}

// ================= argmax + log-softmax-prob per row =================
__global__ __launch_bounds__(256) void k_argmax(int step, float* __restrict__ out){
  const int b = blockIdx.x;
  const int tid = threadIdx.x;
  const float* lg = g_logits[b];
  __shared__ float sv[256];
  __shared__ int   si[256];
  float mv = -1e30f; int mi = 0;
  for(int i=tid;i<VOC;i+=256){ float v = lg[i]; if (v > mv){ mv = v; mi = i; } }
  sv[tid]=mv; si[tid]=mi; __syncthreads();
  for(int o=128;o>0;o>>=1){
    if (tid < o){
      float ov = sv[tid+o]; int oi = si[tid+o];
      if (ov > sv[tid] || (ov == sv[tid] && oi < si[tid])){ sv[tid]=ov; si[tid]=oi; }
    }
    __syncthreads();
  }
  const float gmax = sv[0]; const int gidx = si[0];
  __syncthreads();
  float ls = 0.f;
  for(int i=tid;i<VOC;i+=256) ls += expf(lg[i] - gmax);
  sv[tid] = ls; __syncthreads();
  for(int o=128;o>0;o>>=1){ if (tid < o) sv[tid] += sv[tid+o]; __syncthreads(); }
  if (tid == 0){
    float sel = 1.f / sv[0];                 // exp(lmax - LSE)
    float lp = logf(sel + 1e-12f);
    out[b*TLEN + step] = (float)gidx;        // tokens block
    out[BATCH*TLEN + b*TLEN + step] = lp;    // log-prob block
    g_prev[b] = gidx;
  }
}

// ================= launch =================
extern "C" void kernel_launch(void* const* d_in, const int* in_sizes, int n_in,
                              void* d_out, int out_size) {
  const int*   ids   = (const int*)  d_in[0];
  const float* ctxv  = (const float*)d_in[1];
  const float* emb   = (const float*)d_in[2];
  const float* ewihf = (const float*)d_in[3];
  const float* ewhhf = (const float*)d_in[4];
  const float* ebihf = (const float*)d_in[5];
  const float* ebhhf = (const float*)d_in[6];
  const float* ewihb = (const float*)d_in[7];
  const float* ewhhb = (const float*)d_in[8];
  const float* ebihb = (const float*)d_in[9];
  const float* ebhhb = (const float*)d_in[10];
  const float* dwih  = (const float*)d_in[11];
  const float* dwhh  = (const float*)d_in[12];
  const float* dbih  = (const float*)d_in[13];
  const float* dbhh  = (const float*)d_in[14];
  const float* wout  = (const float*)d_in[15];
  const float* bout  = (const float*)d_in[16];
  float* out = (float*)d_out;

  k_init<<<1024, 256>>>();
  // encoder gate-x for all steps, both directions
  k_encx<<<dim3(G2D/64, (SEQ*BATCH)/64, 2), 256>>>(ids, emb, ewihf, ebihf, ewihb, ebihb);
  // encoder recurrence
  for (int s = 0; s < SEQ; s++)
    k_encstep<<<dim3(H2D/16, BATCH/64, 2), 256>>>(s, ewhhf, ebhhf, ewhhb, ebhhb);
  // decoder constant gx part (includes bih); uses final h at pingpong 0 (SEQ even)
  k_cgx<<<dim3(G3D/64, BATCH/64), 256>>>(ctxv, dwih, dbih);
  // decoder greedy loop
  for (int t = 0; t < TLEN; t++){
    k_dec<<<dim3(HIDD/16, BATCH/64), 256>>>(t, emb, dwih, dwhh, dbhh);
    k_logits<<<dim3(VOC/64, BATCH/64), 256>>>((t+1)&1, wout, bout);
    k_argmax<<<BATCH, 256>>>(t, out);
  }
}

// round 3
// speedup vs baseline: 1.8601x; 1.8601x over previous
#include <cuda_runtime.h>
#include <cuda_bf16.h>
#include <cstdint>

typedef unsigned long long ull;

#define BATCH 256
#define SEQ   128
#define EMBD  512
#define H2D   512
#define G2D   1536
#define HIDD  1024
#define G3D   3072
#define CTXDIM 64
#define VOC   32000
#define TLEN  40
#define SOSID 2

// ---------------- scratch (device globals: no runtime allocation) ----------------
__device__ float g_gx[2][SEQ*BATCH][G2D];   // encoder gate-x per step (bias included)
__device__ float g_h[2][2][BATCH*H2D];      // [dir][pingpong][b*512+u]
__device__ float g_cgx[BATCH][G3D];         // decoder constant part of gx (ctx @ W + bih)
__device__ float g_hd[2][BATCH*HIDD];       // decoder hidden ping-pong
__device__ float g_logits[BATCH][VOC];
__device__ int   g_prev[BATCH];
__device__ __align__(16) __nv_bfloat16 g_wbf[VOC*HIDD];   // bf16 copy of wout
__device__ __align__(16) __nv_bfloat16 g_hbf[BATCH*HIDD]; // bf16 copy of current decoder h

// ---------------- helpers ----------------
__device__ __forceinline__ ull pk2(float lo, float hi){ ull r; asm("mov.b64 %0,{%1,%2};":"=l"(r):"f"(lo),"f"(hi)); return r; }
__device__ __forceinline__ void upk2(ull v, float& lo, float& hi){ asm("mov.b64 {%0,%1},%2;":"=f"(lo),"=f"(hi):"l"(v)); }
__device__ __forceinline__ ull ffma2(ull a, ull b, ull c){ ull d; asm("fma.rn.f32x2 %0,%1,%2,%3;":"=l"(d):"l"(a),"l"(b),"l"(c)); return d; }
__device__ __forceinline__ float sigf(float x){ return 1.0f/(1.0f + expf(-x)); }
__device__ __forceinline__ uint32_t s2u(const void* p){
  uint32_t a; asm("{ .reg .u64 t; cvta.to.shared.u64 t, %1; cvt.u32.u64 %0, t; }":"=r"(a):"l"(p)); return a;
}
__device__ __forceinline__ void ldmx4(uint32_t& r0,uint32_t& r1,uint32_t& r2,uint32_t& r3, uint32_t addr){
  asm volatile("ldmatrix.sync.aligned.m8n8.x4.shared.b16 {%0,%1,%2,%3}, [%4];"
    :"=r"(r0),"=r"(r1),"=r"(r2),"=r"(r3):"r"(addr));
}
__device__ __forceinline__ void mma16816(float* d, uint32_t a0,uint32_t a1,uint32_t a2,uint32_t a3, uint32_t b0,uint32_t b1){
  asm volatile("mma.sync.aligned.m16n8k16.row.col.f32.bf16.bf16.f32 "
    "{%0,%1,%2,%3}, {%4,%5,%6,%7}, {%8,%9}, {%0,%1,%2,%3};"
    :"+f"(d[0]),"+f"(d[1]),"+f"(d[2]),"+f"(d[3])
    :"r"(a0),"r"(a1),"r"(a2),"r"(a3),"r"(b0),"r"(b1));
}

// ---------------- init ----------------
__global__ __launch_bounds__(256) void k_init(){
  int i = blockIdx.x*blockDim.x + threadIdx.x;
  if (i < BATCH*H2D){ g_h[0][0][i] = 0.f; g_h[1][0][i] = 0.f; }
  if (i < BATCH*HIDD) g_hd[0][i] = 0.f;
  if (i < BATCH) g_prev[i] = SOSID;
}

// ---------------- wout -> bf16 ----------------
__global__ __launch_bounds__(256) void k_wconv(const float* __restrict__ w){
  size_t i = (size_t)blockIdx.x*256 + threadIdx.x;
  float4 v = ((const float4*)w)[i];
  __nv_bfloat162* dst = (__nv_bfloat162*)g_wbf;
  dst[2*i]   = __floats2bfloat162_rn(v.x, v.y);
  dst[2*i+1] = __floats2bfloat162_rn(v.z, v.w);
}

// ================= encoder input GEMM (fused embedding gather) =================
__global__ __launch_bounds__(256) void k_encx(const int* __restrict__ ids, const float* __restrict__ emb,
      const float* __restrict__ wf, const float* __restrict__ bf,
      const float* __restrict__ wb, const float* __restrict__ bbias){
  const int dir = blockIdx.z;
  const float* W    = dir ? wb : wf;
  const float* bias = dir ? bbias : bf;
  __shared__ float As[16][68];
  __shared__ float Bs[16][68];
  const int t = threadIdx.x;
  const int m0 = blockIdx.y*64, n0 = blockIdx.x*64;
  const int lr = t>>2, lk4 = (t&3)*4;
  const int tx = t&15, ty = t>>4;
  const int r  = m0 + lr;
  const int ss = r >> 8, bv = r & 255;
  const int sstep = dir ? (SEQ-1-ss) : ss;
  const float* arow = emb + (size_t)ids[bv*SEQ + sstep]*EMBD;
  const float* brow = W + (size_t)(n0+lr)*EMBD;
  ull acc[4][2];
  #pragma unroll
  for(int i=0;i<4;i++){acc[i][0]=0ull;acc[i][1]=0ull;}
  for(int k0=0;k0<EMBD;k0+=16){
    float4 av = *(const float4*)(arow + k0 + lk4);
    As[lk4+0][lr]=av.x; As[lk4+1][lr]=av.y; As[lk4+2][lr]=av.z; As[lk4+3][lr]=av.w;
    float4 bv4 = *(const float4*)(brow + k0 + lk4);
    Bs[lk4+0][lr]=bv4.x; Bs[lk4+1][lr]=bv4.y; Bs[lk4+2][lr]=bv4.z; Bs[lk4+3][lr]=bv4.w;
    __syncthreads();
    #pragma unroll
    for(int k=0;k<16;k++){
      float4 a = *(const float4*)&As[k][ty*4];
      float4 b = *(const float4*)&Bs[k][tx*4];
      ull b01 = pk2(b.x,b.y), b23 = pk2(b.z,b.w);
      ull a0=pk2(a.x,a.x), a1=pk2(a.y,a.y), a2=pk2(a.z,a.z), a3=pk2(a.w,a.w);
      acc[0][0]=ffma2(a0,b01,acc[0][0]); acc[0][1]=ffma2(a0,b23,acc[0][1]);
      acc[1][0]=ffma2(a1,b01,acc[1][0]); acc[1][1]=ffma2(a1,b23,acc[1][1]);
      acc[2][0]=ffma2(a2,b01,acc[2][0]); acc[2][1]=ffma2(a2,b23,acc[2][1]);
      acc[3][0]=ffma2(a3,b01,acc[3][0]); acc[3][1]=ffma2(a3,b23,acc[3][1]);
    }
    __syncthreads();
  }
  const int c0 = n0 + tx*4;
  float4 b4 = *(const float4*)(bias + c0);
  #pragma unroll
  for(int i=0;i<4;i++){
    int row = m0 + ty*4 + i;
    float4 o; upk2(acc[i][0], o.x, o.y); upk2(acc[i][1], o.z, o.w);
    o.x+=b4.x; o.y+=b4.y; o.z+=b4.z; o.w+=b4.w;
    *(float4*)&g_gx[dir][row][c0] = o;
  }
}

// ================= encoder recurrence step =================
__global__ __launch_bounds__(256) void k_encstep(int s,
      const float* __restrict__ whf, const float* __restrict__ bhf,
      const float* __restrict__ whb, const float* __restrict__ bhb){
  const int dir = blockIdx.z;
  const float* whh = dir ? whb : whf;
  const float* bhh = dir ? bhb : bhf;
  const int pin = s & 1, pout = pin ^ 1;
  const float* hin = g_h[dir][pin];
  float* hout = g_h[dir][pout];
  __shared__ float hs[16][68];
  __shared__ float ws[16][48];
  const int t = threadIdx.x;
  const int u0 = blockIdx.x*16, m0 = blockIdx.y*64;
  const int lr = t>>2, lk4 = (t&3)*4;
  const int unit = t&15, rg = t>>4;
  ull ar[2]={0ull,0ull}, az[2]={0ull,0ull}, an[2]={0ull,0ull};
  const int gr = t>>2;
  const int uu = gr/3, gg = gr%3;
  for(int k0=0;k0<H2D;k0+=16){
    float4 av = *(const float4*)(hin + (m0+lr)*H2D + k0 + lk4);
    hs[lk4+0][lr]=av.x; hs[lk4+1][lr]=av.y; hs[lk4+2][lr]=av.z; hs[lk4+3][lr]=av.w;
    if (t < 192){
      float4 wv = *(const float4*)(whh + (size_t)(gg*H2D + u0 + uu)*H2D + k0 + lk4);
      ws[lk4+0][gr]=wv.x; ws[lk4+1][gr]=wv.y; ws[lk4+2][gr]=wv.z; ws[lk4+3][gr]=wv.w;
    }
    __syncthreads();
    #pragma unroll
    for(int k=0;k<16;k++){
      float4 a = *(const float4*)&hs[k][rg*4];
      ull a01 = pk2(a.x,a.y), a23 = pk2(a.z,a.w);
      float wr=ws[k][unit*3+0], wz=ws[k][unit*3+1], wn=ws[k][unit*3+2];
      ull wr2=pk2(wr,wr), wz2=pk2(wz,wz), wn2=pk2(wn,wn);
      ar[0]=ffma2(a01,wr2,ar[0]); ar[1]=ffma2(a23,wr2,ar[1]);
      az[0]=ffma2(a01,wz2,az[0]); az[1]=ffma2(a23,wz2,az[1]);
      an[0]=ffma2(a01,wn2,an[0]); an[1]=ffma2(a23,wn2,an[1]);
    }
    __syncthreads();
  }
  const int u = u0 + unit;
  const float bhr = bhh[u], bhz = bhh[H2D+u], bhn = bhh[2*H2D+u];
  float rr[4], zz[4], nn[4];
  upk2(ar[0],rr[0],rr[1]); upk2(ar[1],rr[2],rr[3]);
  upk2(az[0],zz[0],zz[1]); upk2(az[1],zz[2],zz[3]);
  upk2(an[0],nn[0],nn[1]); upk2(an[1],nn[2],nn[3]);
  #pragma unroll
  for(int i=0;i<4;i++){
    const int row = m0 + rg*4 + i;
    const float* gx = g_gx[dir][s*BATCH + row];
    float ghr = rr[i]+bhr, ghz = zz[i]+bhz, ghn = nn[i]+bhn;
    float r_ = sigf(gx[u] + ghr);
    float z_ = sigf(gx[H2D+u] + ghz);
    float n_ = tanhf(gx[2*H2D+u] + r_*ghn);
    float ho = hin[row*H2D + u];
    hout[row*H2D + u] = (1.f - z_)*n_ + z_*ho;
  }
}

// ================= decoder constant gx: cgx = [enc_ctx | ctxv] @ Wih[:,512:].T + bih =================
__global__ __launch_bounds__(256) void k_cgx(const float* __restrict__ ctxv,
      const float* __restrict__ dwih, const float* __restrict__ dbih){
  __shared__ float As[16][68];
  __shared__ float Bs[16][68];
  const int t = threadIdx.x;
  const int m0 = blockIdx.y*64, n0 = blockIdx.x*64;
  const int lr = t>>2, lk4 = (t&3)*4;
  const int tx = t&15, ty = t>>4;
  const int b  = m0 + lr;
  const float* brow = dwih + (size_t)(n0+lr)*1600 + 512;
  ull acc[4][2];
  #pragma unroll
  for(int i=0;i<4;i++){acc[i][0]=0ull;acc[i][1]=0ull;}
  for(int k0=0;k0<1088;k0+=16){
    int j = k0 + lk4;
    float4 av;
    if (j < 1024){
      const float* hsrc = (b < 128) ? g_h[0][0] : g_h[1][0];
      int b2 = (b < 128) ? b : b - 128;
      av = *(const float4*)(hsrc + (2*b2 + (j>=512 ? 1 : 0))*H2D + (j & 511));
    } else {
      av = *(const float4*)(ctxv + b*CTXDIM + (j - 1024));
    }
    As[lk4+0][lr]=av.x; As[lk4+1][lr]=av.y; As[lk4+2][lr]=av.z; As[lk4+3][lr]=av.w;
    float4 bv = *(const float4*)(brow + k0 + lk4);
    Bs[lk4+0][lr]=bv.x; Bs[lk4+1][lr]=bv.y; Bs[lk4+2][lr]=bv.z; Bs[lk4+3][lr]=bv.w;
    __syncthreads();
    #pragma unroll
    for(int k=0;k<16;k++){
      float4 a = *(const float4*)&As[k][ty*4];
      float4 b4 = *(const float4*)&Bs[k][tx*4];
      ull b01 = pk2(b4.x,b4.y), b23 = pk2(b4.z,b4.w);
      ull a0=pk2(a.x,a.x), a1=pk2(a.y,a.y), a2=pk2(a.z,a.z), a3=pk2(a.w,a.w);
      acc[0][0]=ffma2(a0,b01,acc[0][0]); acc[0][1]=ffma2(a0,b23,acc[0][1]);
      acc[1][0]=ffma2(a1,b01,acc[1][0]); acc[1][1]=ffma2(a1,b23,acc[1][1]);
      acc[2][0]=ffma2(a2,b01,acc[2][0]); acc[2][1]=ffma2(a2,b23,acc[2][1]);
      acc[3][0]=ffma2(a3,b01,acc[3][0]); acc[3][1]=ffma2(a3,b23,acc[3][1]);
    }
    __syncthreads();
  }
  const int c0 = n0 + tx*4;
  float4 b4 = *(const float4*)(dbih + c0);
  #pragma unroll
  for(int i=0;i<4;i++){
    int row = m0 + ty*4 + i;
    float4 o; upk2(acc[i][0], o.x, o.y); upk2(acc[i][1], o.z, o.w);
    o.x+=b4.x; o.y+=b4.y; o.z+=b4.z; o.w+=b4.w;
    *(float4*)&g_cgx[row][c0] = o;
  }
}

// ================= decoder step: fused GRU =================
__global__ __launch_bounds__(256) void k_dec(int step, const float* __restrict__ emb,
      const float* __restrict__ dwih, const float* __restrict__ dwhh, const float* __restrict__ dbhh){
  const int pin = step & 1, pout = pin ^ 1;
  const float* hin = g_hd[pin];
  float* hout = g_hd[pout];
  __shared__ float xs[16][68];
  __shared__ float ws[16][48];
  __shared__ int pid_s[64];
  const int t = threadIdx.x;
  const int u0 = blockIdx.x*16, m0 = blockIdx.y*64;
  if (t < 64) pid_s[t] = g_prev[m0 + t];
  const int lr = t>>2, lk4 = (t&3)*4;
  const int unit = t&15, rg = t>>4;
  const int gr = t>>2;
  const int uu = gr/3, gg = gr%3;
  ull xr[2]={0ull,0ull}, xz[2]={0ull,0ull}, xn[2]={0ull,0ull};
  ull hr[2]={0ull,0ull}, hz[2]={0ull,0ull}, hn[2]={0ull,0ull};
  __syncthreads();
  const float* arow = emb + (size_t)pid_s[lr]*EMBD;
  for(int k0=0;k0<EMBD;k0+=16){
    float4 av = *(const float4*)(arow + k0 + lk4);
    xs[lk4+0][lr]=av.x; xs[lk4+1][lr]=av.y; xs[lk4+2][lr]=av.z; xs[lk4+3][lr]=av.w;
    if (t < 192){
      float4 wv = *(const float4*)(dwih + (size_t)(gg*HIDD + u0 + uu)*1600 + k0 + lk4);
      ws[lk4+0][gr]=wv.x; ws[lk4+1][gr]=wv.y; ws[lk4+2][gr]=wv.z; ws[lk4+3][gr]=wv.w;
    }
    __syncthreads();
    #pragma unroll
    for(int k=0;k<16;k++){
      float4 a = *(const float4*)&xs[k][rg*4];
      ull a01 = pk2(a.x,a.y), a23 = pk2(a.z,a.w);
      float wr=ws[k][unit*3+0], wzv=ws[k][unit*3+1], wnv=ws[k][unit*3+2];
      ull wr2=pk2(wr,wr), wz2=pk2(wzv,wzv), wn2=pk2(wnv,wnv);
      xr[0]=ffma2(a01,wr2,xr[0]); xr[1]=ffma2(a23,wr2,xr[1]);
      xz[0]=ffma2(a01,wz2,xz[0]); xz[1]=ffma2(a23,wz2,xz[1]);
      xn[0]=ffma2(a01,wn2,xn[0]); xn[1]=ffma2(a23,wn2,xn[1]);
    }
    __syncthreads();
  }
  for(int k0=0;k0<HIDD;k0+=16){
    float4 av = *(const float4*)(hin + (m0+lr)*HIDD + k0 + lk4);
    xs[lk4+0][lr]=av.x; xs[lk4+1][lr]=av.y; xs[lk4+2][lr]=av.z; xs[lk4+3][lr]=av.w;
    if (t < 192){
      float4 wv = *(const float4*)(dwhh + (size_t)(gg*HIDD + u0 + uu)*HIDD + k0 + lk4);
      ws[lk4+0][gr]=wv.x; ws[lk4+1][gr]=wv.y; ws[lk4+2][gr]=wv.z; ws[lk4+3][gr]=wv.w;
    }
    __syncthreads();
    #pragma unroll
    for(int k=0;k<16;k++){
      float4 a = *(const float4*)&xs[k][rg*4];
      ull a01 = pk2(a.x,a.y), a23 = pk2(a.z,a.w);
      float wr=ws[k][unit*3+0], wzv=ws[k][unit*3+1], wnv=ws[k][unit*3+2];
      ull wr2=pk2(wr,wr), wz2=pk2(wzv,wzv), wn2=pk2(wnv,wnv);
      hr[0]=ffma2(a01,wr2,hr[0]); hr[1]=ffma2(a23,wr2,hr[1]);
      hz[0]=ffma2(a01,wz2,hz[0]); hz[1]=ffma2(a23,wz2,hz[1]);
      hn[0]=ffma2(a01,wn2,hn[0]); hn[1]=ffma2(a23,wn2,hn[1]);
    }
    __syncthreads();
  }
  const int u = u0 + unit;
  const float bhr = dbhh[u], bhz = dbhh[HIDD+u], bhn = dbhh[2*HIDD+u];
  float fxr[4],fxz[4],fxn[4],fhr[4],fhz[4],fhn[4];
  upk2(xr[0],fxr[0],fxr[1]); upk2(xr[1],fxr[2],fxr[3]);
  upk2(xz[0],fxz[0],fxz[1]); upk2(xz[1],fxz[2],fxz[3]);
  upk2(xn[0],fxn[0],fxn[1]); upk2(xn[1],fxn[2],fxn[3]);
  upk2(hr[0],fhr[0],fhr[1]); upk2(hr[1],fhr[2],fhr[3]);
  upk2(hz[0],fhz[0],fhz[1]); upk2(hz[1],fhz[2],fhz[3]);
  upk2(hn[0],fhn[0],fhn[1]); upk2(hn[1],fhn[2],fhn[3]);
  #pragma unroll
  for(int i=0;i<4;i++){
    const int row = m0 + rg*4 + i;
    const float* cg = g_cgx[row];
    float gxr = fxr[i] + cg[u];
    float gxz = fxz[i] + cg[HIDD+u];
    float gxn = fxn[i] + cg[2*HIDD+u];
    float ghr = fhr[i] + bhr, ghz = fhz[i] + bhz, ghn = fhn[i] + bhn;
    float r_ = sigf(gxr + ghr);
    float z_ = sigf(gxz + ghz);
    float n_ = tanhf(gxn + r_*ghn);
    float ho = hin[row*HIDD + u];
    float hv = (1.f - z_)*n_ + z_*ho;
    hout[row*HIDD + u] = hv;
    g_hbf[row*HIDD + u] = __float2bfloat16(hv);
  }
}

// ================= logits via bf16 HMMA (mma.sync m16n8k16) =================
// CTA tile M=128 x N=128, K chunks of 64. 8 warps (2x4), each m64 x n32.
__global__ __launch_bounds__(256) void k_loghmma(const float* __restrict__ bout){
  __shared__ __align__(1024) char Asm[16384];
  __shared__ __align__(1024) char Bsm[16384];
  const int t = threadIdx.x;
  const int lane = t&31, wid = t>>5;
  const int mblk = blockIdx.y*128, nblk = blockIdx.x*128;
  const int mbase = (wid&1)*64, nbase = (wid>>1)*32;
  const uint32_t Au = s2u(Asm), Bu = s2u(Bsm);
  float acc[4][4][4];
  #pragma unroll
  for(int mt=0;mt<4;mt++)
    #pragma unroll
    for(int nt=0;nt<4;nt++)
      #pragma unroll
      for(int e=0;e<4;e++) acc[mt][nt][e]=0.f;

  // precomputed swizzled ldmatrix offsets (per lane)
  uint32_t aoff[4], boff[2];
  #pragma unroll
  for(int mt=0;mt<4;mt++){
    uint32_t row = mbase + mt*16 + (lane&15);
    uint32_t off = row*128 + (lane>>4)*16;
    aoff[mt] = off ^ ((off>>3)&0x70);
  }
  #pragma unroll
  for(int nt2=0;nt2<2;nt2++){
    uint32_t row = nbase + nt2*16 + (lane&7) + ((lane>>4)&1)*8;
    uint32_t off = row*128 + ((lane>>3)&1)*16;
    boff[nt2] = off ^ ((off>>3)&0x70);
  }

  for(int c=0;c<16;c++){
    #pragma unroll
    for(int i=0;i<4;i++){
      int idx = t + i*256;
      int row = idx>>3, unit = idx&7;
      uint32_t off = row*128 + unit*16;
      uint32_t sw = off ^ ((off>>3)&0x70);
      *(uint4*)(Asm + sw) = *(const uint4*)((const char*)g_hbf + (size_t)(mblk+row)*2048 + c*128 + unit*16);
      *(uint4*)(Bsm + sw) = *(const uint4*)((const char*)g_wbf + (size_t)(nblk+row)*2048 + c*128 + unit*16);
    }
    __syncthreads();
    #pragma unroll
    for(int ks=0;ks<4;ks++){
      // swizzle-XOR trick: moving by 32B within a row flips bit5 of the 16B-unit
      // index pre-swizzle; since swizzle only XORs bits[6:4] with row bits, adding
      // ks*32 bytes pre-swizzle == XOR of (ks*32) post-swizzle only when no carry.
      // units 2*ks and 2*ks+1 differ from base units 0/1 by XOR with (2*ks)<<4.
      const uint32_t kx = (uint32_t)(ks<<5);
      uint32_t a[4][4], b[2][4];
      #pragma unroll
      for(int mt=0;mt<4;mt++)
        ldmx4(a[mt][0],a[mt][1],a[mt][2],a[mt][3], Au + (aoff[mt]^kx));
      #pragma unroll
      for(int nt2=0;nt2<2;nt2++)
        ldmx4(b[nt2][0],b[nt2][1],b[nt2][2],b[nt2][3], Bu + (boff[nt2]^kx));
      #pragma unroll
      for(int mt=0;mt<4;mt++)
        #pragma unroll
        for(int nt=0;nt<4;nt++)
          mma16816(acc[mt][nt], a[mt][0],a[mt][1],a[mt][2],a[mt][3],
                   b[nt>>1][(nt&1)*2], b[nt>>1][(nt&1)*2+1]);
    }
    __syncthreads();
  }
  #pragma unroll
  for(int mt=0;mt<4;mt++){
    int r0 = mblk + mbase + mt*16 + (lane>>2);
    #pragma unroll
    for(int nt=0;nt<4;nt++){
      int c0 = nblk + nbase + nt*8 + (lane&3)*2;
      float b0v = bout[c0], b1v = bout[c0+1];
      g_logits[r0][c0]     = acc[mt][nt][0] + b0v;
      g_logits[r0][c0+1]   = acc[mt][nt][1] + b1v;
      g_logits[r0+8][c0]   = acc[mt][nt][2] + b0v;
      g_logits[r0+8][c0+1] = acc[mt][nt][3] + b1v;
    }
  }
}

// ================= argmax with exact fp32 rescore + log-softmax =================
__global__ __launch_bounds__(256) void k_argmax(int step, int pp,
      const float* __restrict__ wout, const float* __restrict__ bout, float* __restrict__ out){
  const int b = blockIdx.x, tid = threadIdx.x;
  const int wid = tid>>5, lane = tid&31;
  const float* lg = g_logits[b];
  __shared__ float sv[256]; __shared__ int si[256];
  __shared__ float s1[256], s2a[256];
  float mv=-1e30f; int mi=0; float a1=0.f, a2=0.f;
  for (int i=tid;i<VOC;i+=256){ float v=lg[i]; a1+=v; a2+=v*v; if(v>mv){mv=v;mi=i;} }
  sv[tid]=mv; si[tid]=mi; s1[tid]=a1; s2a[tid]=a2; __syncthreads();
  for(int o=128;o>0;o>>=1){
    if(tid<o){
      if(sv[tid+o]>sv[tid]||(sv[tid+o]==sv[tid]&&si[tid+o]<si[tid])){sv[tid]=sv[tid+o];si[tid]=si[tid+o];}
      s1[tid]+=s1[tid+o]; s2a[tid]+=s2a[tid+o];
    }
    __syncthreads();
  }
  const float gmax=sv[0]; const int gidx=si[0];
  const float mean=s1[0]/VOC;
  const float var=fmaxf(s2a[0]/VOC-mean*mean,0.f);
  const float margin=0.05f*sqrtf(var)+1e-6f;
  __shared__ int cnt; __shared__ int cands[128]; __shared__ float cval[128];
  if(tid==0){cnt=1;cands[0]=gidx;}
  __syncthreads();
  for(int i=tid;i<VOC;i+=256){
    if(lg[i]>=gmax-margin && i!=gidx){ int p=atomicAdd(&cnt,1); if(p<128) cands[p]=i; }
  }
  float ls=0.f;
  for(int i=tid;i<VOC;i+=256) ls+=expf(lg[i]-gmax);
  sv[tid]=ls; __syncthreads();
  for(int o=128;o>0;o>>=1){ if(tid<o) sv[tid]+=sv[tid+o]; __syncthreads(); }
  const float ssum=sv[0];
  const int nc = min(cnt,128);
  const float* hrow = g_hd[pp] + (size_t)b*HIDD;
  for(int j=wid;j<nc;j+=8){
    const float* wr = wout + (size_t)cands[j]*HIDD;
    float s=0.f;
    for(int k=lane;k<HIDD;k+=32) s += hrow[k]*wr[k];
    #pragma unroll
    for(int o=16;o>0;o>>=1) s += __shfl_xor_sync(0xffffffffu,s,o);
    if(lane==0) cval[j]=s+bout[cands[j]];
  }
  __syncthreads();
  if(tid==0){
    float best=-1e30f; int bi=VOC;
    for(int j=0;j<nc;j++){
      float v=cval[j]; int id=cands[j];
      if(v>best||(v==best&&id<bi)){best=v;bi=id;}
    }
    float sel = expf(best-gmax)/ssum;
    float lp = logf(sel+1e-12f);
    out[b*TLEN+step]=(float)bi;
    out[BATCH*TLEN+b*TLEN+step]=lp;
    g_prev[b]=bi;
  }
}

// ================= launch =================
extern "C" void kernel_launch(void* const* d_in, const int* in_sizes, int n_in,
                              void* d_out, int out_size) {
  const int*   ids   = (const int*)  d_in[0];
  const float* ctxv  = (const float*)d_in[1];
  const float* emb   = (const float*)d_in[2];
  const float* ewihf = (const float*)d_in[3];
  const float* ewhhf = (const float*)d_in[4];
  const float* ebihf = (const float*)d_in[5];
  const float* ebhhf = (const float*)d_in[6];
  const float* ewihb = (const float*)d_in[7];
  const float* ewhhb = (const float*)d_in[8];
  const float* ebihb = (const float*)d_in[9];
  const float* ebhhb = (const float*)d_in[10];
  const float* dwih  = (const float*)d_in[11];
  const float* dwhh  = (const float*)d_in[12];
  const float* dbih  = (const float*)d_in[13];
  const float* dbhh  = (const float*)d_in[14];
  const float* wout  = (const float*)d_in[15];
  const float* bout  = (const float*)d_in[16];
  float* out = (float*)d_out;

  k_init<<<1024, 256>>>();
  k_wconv<<<VOC*HIDD/1024, 256>>>(wout);
  k_encx<<<dim3(G2D/64, (SEQ*BATCH)/64, 2), 256>>>(ids, emb, ewihf, ebihf, ewihb, ebihb);
  for (int s = 0; s < SEQ; s++)
    k_encstep<<<dim3(H2D/16, BATCH/64, 2), 256>>>(s, ewhhf, ebhhf, ewhhb, ebhhb);
  k_cgx<<<dim3(G3D/64, BATCH/64), 256>>>(ctxv, dwih, dbih);
  for (int t = 0; t < TLEN; t++){
    k_dec<<<dim3(HIDD/16, BATCH/64), 256>>>(t, emb, dwih, dwhh, dbhh);
    k_loghmma<<<dim3(VOC/128, BATCH/128), 256>>>(bout);
    k_argmax<<<BATCH, 256>>>(t, (t+1)&1, wout, bout, out);
  }
}